// round 2
// baseline (speedup 1.0000x reference)
#include <cuda_runtime.h>
#include <cuda_bf16.h>

// Problem constants (fixed by the dataset)
#define BB 16
#define LL 512
#define DD 256
#define FF 256
#define KK 3
#define MM 2048
#define EPSV 1e-5f

// Scratch (device globals — no allocation allowed)
__device__ float g_w1t[KK * DD * FF];       // transposed conv1 weight: [(k*D+d)][f]
__device__ float g_w2t[KK * FF * FF];       // transposed conv2 weight
__device__ float g_h1[BB * LL * FF];        // conv1 -> LN -> relu output
__device__ float g_h2[BB * LL * FF];        // conv2 -> LN -> relu output
__device__ int   g_cs[BB * LL];             // inclusive cumsum of target

// ---------------------------------------------------------------------------
// Weight transpose: w (F, D, K) -> wt[(k*D+d)*F + f]
// ---------------------------------------------------------------------------
__global__ void prep_transpose(const float* __restrict__ w1,
                               const float* __restrict__ w2,
                               float* __restrict__ w1t,
                               float* __restrict__ w2t) {
    int idx = blockIdx.x * blockDim.x + threadIdx.x;
    if (idx < KK * DD * FF) {
        int f = idx & (FF - 1);
        int j = idx >> 8;            // k*256 + d
        int k = j >> 8;
        int d = j & 255;
        w1t[idx] = w1[f * (DD * KK) + d * KK + k];
        w2t[idx] = w2[f * (FF * KK) + d * KK + k];
    }
}

// ---------------------------------------------------------------------------
// Per-batch inclusive cumsum of durations (L = 512, one block per batch)
// ---------------------------------------------------------------------------
__global__ void cumsum_k(const int* __restrict__ t, int* __restrict__ cs) {
    __shared__ int s[LL];
    int b = blockIdx.x, tid = threadIdx.x;
    s[tid] = t[(b << 9) + tid];
    __syncthreads();
    for (int off = 1; off < LL; off <<= 1) {
        int v = (tid >= off) ? s[tid - off] : 0;
        __syncthreads();
        s[tid] += v;
        __syncthreads();
    }
    cs[(b << 9) + tid] = s[tid];
}

// ---------------------------------------------------------------------------
// Fused conv1d(K=3, SAME) + bias + LayerNorm + ReLU.
// Grid: 256 blocks, each computes 32 rows x 256 cols. 256 threads: thread tx
// owns output column tx for all 32 rows (32 fp32 accumulators).
// Dynamic smem: xs[34][256] input tile w/ halo + ws[32][256] weight chunk.
// ---------------------------------------------------------------------------
__global__ void conv_ln_relu(const float* __restrict__ in,   // (B,L,256)
                             const float* __restrict__ wt,   // (3*256, 256) transposed
                             const float* __restrict__ bias,
                             const float* __restrict__ gamma,
                             const float* __restrict__ beta,
                             float* __restrict__ out) {      // (B,L,256)
    extern __shared__ float sm[];
    float* xs = sm;                  // 34*256
    float* ws = sm + 34 * 256;       // 32*256
    __shared__ float s_mu[32], s_rs[32];

    const int tid = threadIdx.x;
    const int tile = blockIdx.x;          // 0..255
    const int row0 = tile * 32;           // global row = b*512 + l0
    const int b = row0 >> 9;
    const int l0 = row0 & 511;

    // load input tile with halo rows (l0-1 .. l0+32), zero-padded per batch
#pragma unroll
    for (int r = 0; r < 34; r++) {
        int l = l0 - 1 + r;
        float v = 0.f;
        if (l >= 0 && l < LL) v = in[(((b << 9) + l) << 8) + tid];
        xs[r * 256 + tid] = v;
    }

    float acc[32];
#pragma unroll
    for (int i = 0; i < 32; i++) acc[i] = 0.f;

    for (int k = 0; k < 3; k++) {
        for (int d0 = 0; d0 < 256; d0 += 32) {
            __syncthreads();
            // stage 32x256 weight chunk (coalesced)
#pragma unroll
            for (int dd = 0; dd < 32; dd++)
                ws[dd * 256 + tid] = wt[(((k << 8) + d0 + dd) << 8) + tid];
            __syncthreads();
#pragma unroll
            for (int dd0 = 0; dd0 < 32; dd0 += 8) {
                float wr[8];
#pragma unroll
                for (int j = 0; j < 8; j++) wr[j] = ws[(dd0 + j) * 256 + tid];
#pragma unroll
                for (int i = 0; i < 32; i++) {
                    const float4* xp = reinterpret_cast<const float4*>(
                        &xs[(i + k) * 256 + d0 + dd0]);
                    float4 x0 = xp[0];
                    float4 x1 = xp[1];
                    float a = acc[i];
                    a = fmaf(x0.x, wr[0], a);
                    a = fmaf(x0.y, wr[1], a);
                    a = fmaf(x0.z, wr[2], a);
                    a = fmaf(x0.w, wr[3], a);
                    a = fmaf(x1.x, wr[4], a);
                    a = fmaf(x1.y, wr[5], a);
                    a = fmaf(x1.z, wr[6], a);
                    a = fmaf(x1.w, wr[7], a);
                    acc[i] = a;
                }
            }
        }
    }

    const float bv = bias[tid];
#pragma unroll
    for (int i = 0; i < 32; i++) acc[i] += bv;

    // LayerNorm over the 256 columns of each row (stats via smem + warp reduce)
    __syncthreads();
#pragma unroll
    for (int i = 0; i < 32; i++) ws[i * 256 + tid] = acc[i];
    __syncthreads();

    const int warp = tid >> 5, lane = tid & 31;
    for (int i = warp; i < 32; i += 8) {
        float s = 0.f, ss = 0.f;
#pragma unroll
        for (int c = lane; c < 256; c += 32) {
            float v = ws[i * 256 + c];
            s += v;
            ss += v * v;
        }
#pragma unroll
        for (int o = 16; o > 0; o >>= 1) {
            s += __shfl_xor_sync(0xffffffffu, s, o);
            ss += __shfl_xor_sync(0xffffffffu, ss, o);
        }
        if (lane == 0) {
            float mu = s * (1.f / 256.f);
            float var = ss * (1.f / 256.f) - mu * mu;
            s_mu[i] = mu;
            s_rs[i] = rsqrtf(var + EPSV);
        }
    }
    __syncthreads();

    const float gv = gamma[tid], btv = beta[tid];
#pragma unroll
    for (int i = 0; i < 32; i++) {
        float v = (acc[i] - s_mu[i]) * s_rs[i] * gv + btv;
        out[((row0 + i) << 8) + tid] = fmaxf(v, 0.f);
    }
}

// ---------------------------------------------------------------------------
// dup[b,l] = relu(h2[b,l,:] . lin_w + lin_b); one warp per row, 8 warps/block
// ---------------------------------------------------------------------------
__global__ void lin_relu(const float* __restrict__ h,
                         const float* __restrict__ lw,
                         const float* __restrict__ lb,
                         float* __restrict__ dup) {
    int warp = threadIdx.x >> 5, lane = threadIdx.x & 31;
    int row = blockIdx.x * 8 + warp;  // 0..8191
    if (row >= BB * LL) return;
    float s = 0.f;
#pragma unroll
    for (int c = lane; c < 256; c += 32)
        s = fmaf(h[(row << 8) + c], lw[c], s);
#pragma unroll
    for (int o = 16; o > 0; o >>= 1) s += __shfl_xor_sync(0xffffffffu, s, o);
    if (lane == 0) dup[row] = fmaxf(s + lb[0], 0.f);
}

// ---------------------------------------------------------------------------
// Length regulate: out[b,m,:] = x[b,l,:] where cs[l-1] <= m < cs[l]; zeros past
// total. One warp per (b, m); binary search over inclusive cumsum.
// ---------------------------------------------------------------------------
__global__ void regulate(const float* __restrict__ x,
                         const int* __restrict__ cs,
                         float* __restrict__ out) {
    int warp = threadIdx.x >> 5, lane = threadIdx.x & 31;
    int gm = blockIdx.x * 8 + warp;   // 0 .. B*M-1
    int b = gm >> 11;                 // / 2048
    int m = gm & (MM - 1);
    const int* c = cs + (b << 9);
    int total = c[LL - 1];
    float4* dst = reinterpret_cast<float4*>(out) + (size_t)gm * 64;
    if (m < total) {
        int lo = 0, hi = LL - 1;
        while (lo < hi) {
            int mid = (lo + hi) >> 1;
            if (c[mid] > m) hi = mid; else lo = mid + 1;
        }
        const float4* src =
            reinterpret_cast<const float4*>(x) + ((size_t)((b << 9) + lo)) * 64;
        dst[lane] = src[lane];
        dst[lane + 32] = src[lane + 32];
    } else {
        float4 z = make_float4(0.f, 0.f, 0.f, 0.f);
        dst[lane] = z;
        dst[lane + 32] = z;
    }
}

// ---------------------------------------------------------------------------
extern "C" void kernel_launch(void* const* d_in, const int* in_sizes, int n_in,
                              void* d_out, int out_size) {
    const float* x      = (const float*)d_in[0];   // (B,L,D)
    const int*   target = (const int*)d_in[1];     // (B,L)
    // d_in[2] = mel_max_length (scalar, fixed 2048)
    const float* w1  = (const float*)d_in[3];
    const float* b1  = (const float*)d_in[4];
    const float* g1  = (const float*)d_in[5];
    const float* be1 = (const float*)d_in[6];
    const float* w2  = (const float*)d_in[7];
    const float* b2  = (const float*)d_in[8];
    const float* g2  = (const float*)d_in[9];
    const float* be2 = (const float*)d_in[10];
    const float* lw  = (const float*)d_in[11];
    const float* lb  = (const float*)d_in[12];

    float* out = (float*)d_out;                         // (B,M,D) first
    float* dup = out + (size_t)BB * MM * DD;            // then (B,L)

    float *w1t, *w2t, *h1, *h2;
    int* cs;
    cudaGetSymbolAddress((void**)&w1t, g_w1t);
    cudaGetSymbolAddress((void**)&w2t, g_w2t);
    cudaGetSymbolAddress((void**)&h1, g_h1);
    cudaGetSymbolAddress((void**)&h2, g_h2);
    cudaGetSymbolAddress((void**)&cs, g_cs);

    const int smem_bytes = (34 * 256 + 32 * 256) * (int)sizeof(float);  // 67584
    cudaFuncSetAttribute((const void*)conv_ln_relu,
                         cudaFuncAttributeMaxDynamicSharedMemorySize, smem_bytes);

    // Weight transpose + cumsum (independent prep)
    prep_transpose<<<(KK * DD * FF + 255) / 256, 256>>>(w1, w2, w1t, w2t);
    cumsum_k<<<BB, LL>>>(target, cs);

    // Length regulate (independent of the conv chain)
    regulate<<<BB * MM / 8, 256>>>(x, cs, out);

    // Duration predictor chain
    conv_ln_relu<<<BB * LL / 32, 256, smem_bytes>>>(x, w1t, b1, g1, be1, h1);
    conv_ln_relu<<<BB * LL / 32, 256, smem_bytes>>>(h1, w2t, b2, g2, be2, h2);
    lin_relu<<<BB * LL / 8, 256>>>(h2, lw, lb, dup);   // 1024 blocks = 8192 rows
}

// round 4
// speedup vs baseline: 2.4127x; 2.4127x over previous
#include <cuda_runtime.h>
#include <cuda_bf16.h>
#include <cstdint>

#define BB 16
#define LL 512
#define DD 256
#define FF 256
#define MM 2048
#define EPSV 1e-5f

// ---------------- device scratch (16B aligned for cp.async/ldmatrix) --------
__device__ __align__(16) __nv_bfloat16 g_xhi[BB * LL * DD];
__device__ __align__(16) __nv_bfloat16 g_xlo[BB * LL * DD];
__device__ __align__(16) __nv_bfloat16 g_h1hi[BB * LL * FF];
__device__ __align__(16) __nv_bfloat16 g_h1lo[BB * LL * FF];
// weights staged as [kc=8][f=256][tap=3][d=32]  (196608 elems each)
__device__ __align__(16) __nv_bfloat16 g_B1h[8 * 256 * 3 * 32];
__device__ __align__(16) __nv_bfloat16 g_B1l[8 * 256 * 3 * 32];
__device__ __align__(16) __nv_bfloat16 g_B2h[8 * 256 * 3 * 32];
__device__ __align__(16) __nv_bfloat16 g_B2l[8 * 256 * 3 * 32];
__device__ int g_cs[BB * LL];

// ---------------- helpers ----------------
__device__ __forceinline__ uint32_t smem_u32(const void* p) {
    uint32_t a;
    asm("{ .reg .u64 t; cvta.to.shared.u64 t, %1; cvt.u32.u64 %0, t; }"
        : "=r"(a) : "l"(p));
    return a;
}

__device__ __forceinline__ void cp16(uint32_t dst, const void* src, int valid) {
    int sz = valid ? 16 : 0;
    asm volatile("cp.async.cg.shared.global [%0], [%1], %2, %3;"
                 :: "r"(dst), "l"(src), "n"(16), "r"(sz));
}
__device__ __forceinline__ void cp_commit() {
    asm volatile("cp.async.commit_group;" ::: "memory");
}
__device__ __forceinline__ void cp_wait1() {
    asm volatile("cp.async.wait_group 1;" ::: "memory");
}
__device__ __forceinline__ void cp_wait0() {
    asm volatile("cp.async.wait_group 0;" ::: "memory");
}

__device__ __forceinline__ void ldsm4(uint32_t* r, uint32_t addr) {
    asm volatile("ldmatrix.sync.aligned.m8n8.x4.shared.b16 {%0,%1,%2,%3}, [%4];"
                 : "=r"(r[0]), "=r"(r[1]), "=r"(r[2]), "=r"(r[3]) : "r"(addr));
}

__device__ __forceinline__ void mma16816(float* d, const uint32_t* a,
                                         const uint32_t* b) {
    asm volatile(
        "mma.sync.aligned.m16n8k16.row.col.f32.bf16.bf16.f32 "
        "{%0,%1,%2,%3}, {%4,%5,%6,%7}, {%8,%9}, {%0,%1,%2,%3};"
        : "+f"(d[0]), "+f"(d[1]), "+f"(d[2]), "+f"(d[3])
        : "r"(a[0]), "r"(a[1]), "r"(a[2]), "r"(a[3]), "r"(b[0]), "r"(b[1]));
}

// ---------------- prep: bf16 hi/lo splits of x and both weights ------------
__global__ void prep_convert(const float* __restrict__ x,
                             const float* __restrict__ w1,
                             const float* __restrict__ w2) {
    int i = blockIdx.x * 256 + threadIdx.x;
    if (i < BB * LL * DD) {
        float v = x[i];
        __nv_bfloat16 h = __float2bfloat16(v);
        g_xhi[i] = h;
        g_xlo[i] = __float2bfloat16(v - __bfloat162float(h));
    }
    if (i < 8 * 256 * 3 * 32) {
        // dst layout [kc][f][tap][32d];  src w[f][d][tap], d = kc*32+d0
        int kc = i / 24576, r = i % 24576;
        int f = r / 96, r2 = r % 96;
        int tap = r2 / 32, d0 = r2 % 32;
        int d = kc * 32 + d0;
        float v1 = w1[f * 768 + d * 3 + tap];
        __nv_bfloat16 h1 = __float2bfloat16(v1);
        g_B1h[i] = h1;
        g_B1l[i] = __float2bfloat16(v1 - __bfloat162float(h1));
        float v2 = w2[f * 768 + d * 3 + tap];
        __nv_bfloat16 h2 = __float2bfloat16(v2);
        g_B2h[i] = h2;
        g_B2l[i] = __float2bfloat16(v2 - __bfloat162float(h2));
    }
}

// ---------------- cumsum ----------------
__global__ void cumsum_k(const int* __restrict__ t, int* __restrict__ cs) {
    __shared__ int s[LL];
    int b = blockIdx.x, tid = threadIdx.x;
    s[tid] = t[(b << 9) + tid];
    __syncthreads();
    for (int off = 1; off < LL; off <<= 1) {
        int v = (tid >= off) ? s[tid - off] : 0;
        __syncthreads();
        s[tid] += v;
        __syncthreads();
    }
    cs[(b << 9) + tid] = s[tid];
}

// ---------------- length regulate (exact) ----------------
__global__ void regulate(const float* __restrict__ x,
                         const int* __restrict__ cs,
                         float* __restrict__ out) {
    int warp = threadIdx.x >> 5, lane = threadIdx.x & 31;
    int gm = blockIdx.x * 8 + warp;
    int b = gm >> 11;
    int m = gm & (MM - 1);
    const int* c = cs + (b << 9);
    int total = c[LL - 1];
    float4* dst = reinterpret_cast<float4*>(out) + (size_t)gm * 64;
    if (m < total) {
        int lo = 0, hi = LL - 1;
        while (lo < hi) {
            int mid = (lo + hi) >> 1;
            if (c[mid] > m) hi = mid; else lo = mid + 1;
        }
        const float4* src =
            reinterpret_cast<const float4*>(x) + ((size_t)((b << 9) + lo)) * 64;
        dst[lane] = src[lane];
        dst[lane + 32] = src[lane + 32];
    } else {
        float4 z = make_float4(0.f, 0.f, 0.f, 0.f);
        dst[lane] = z;
        dst[lane + 32] = z;
    }
}

// ---------------- mma.sync conv(K=3) + bias + LN + ReLU (+linear) ----------
// CTA: 64 rows x 256 channels; 8 warps (2m x 4n), warp tile 32x64.
// A smem: 66 rows x 32 bf16 (+8 pad) = 66*80B; B smem: 256 x (3*32+8) bf16 = 256*208B.
#define S_PAR  0                 // bias/g/be/lw: 4 x 1KB
#define S_BUF0 4096
#define ASZ    (66 * 80)         // 5280
#define BSZ    (256 * 208)       // 53248
#define BUFSZ  (ASZ + BSZ)       // 58528
#define S_TOTAL (4096 + 2 * BUFSZ)  // 121152

__global__ void __launch_bounds__(256, 1)
conv_mma(const __nv_bfloat16* __restrict__ a_hi,
         const __nv_bfloat16* __restrict__ a_lo,
         const __nv_bfloat16* __restrict__ b_hi,
         const __nv_bfloat16* __restrict__ b_lo,
         const float* __restrict__ bias,
         const float* __restrict__ gamma,
         const float* __restrict__ beta,
         int mode,
         __nv_bfloat16* __restrict__ out_hi,
         __nv_bfloat16* __restrict__ out_lo,
         const float* __restrict__ lw,
         const float* __restrict__ lb,
         float* __restrict__ dup) {
    extern __shared__ char sm[];
    const uint32_t sb = smem_u32(sm);
    const int tid = threadIdx.x;
    const int lane = tid & 31;
    const int wid = tid >> 5;
    const int wm = wid & 1;          // m half: 0/1 -> rows 0-31 / 32-63
    const int wn = wid >> 1;         // n quarter: 0..3 -> cols wn*64
    const int row0 = blockIdx.x * 64;
    const int l0 = row0 & 511;

    float* s_bias = (float*)(sm + S_PAR);
    float* s_g = (float*)(sm + S_PAR + 1024);
    float* s_be = (float*)(sm + S_PAR + 2048);
    float* s_lw = (float*)(sm + S_PAR + 3072);
    s_bias[tid] = bias[tid];
    s_g[tid] = gamma[tid];
    s_be[tid] = beta[tid];
    s_lw[tid] = (mode == 1) ? lw[tid] : 0.f;

    // per-lane ldmatrix base offsets (bytes)
    const uint32_t aL = (uint32_t)((wm * 32 + (lane & 15)) * 80 + (lane >> 4) * 16);
    const uint32_t bL = (uint32_t)((wn * 64 + (lane & 7) + ((lane >> 4) << 3)) * 208 +
                                   ((lane >> 3) & 1) * 16);

    float d[2][8][4];
#pragma unroll
    for (int tm = 0; tm < 2; tm++)
#pragma unroll
        for (int tn = 0; tn < 8; tn++)
#pragma unroll
            for (int j = 0; j < 4; j++) d[tm][tn][j] = 0.f;

    // -------- staging lambda (cp.async) --------
    auto stage = [&](int it) {
        int p = it >> 3, kc = it & 7, buf = it & 1;
        const __nv_bfloat16* ap = (p < 2) ? a_hi : a_lo;   // hh, hl, lh
        const __nv_bfloat16* bp = (p == 1) ? b_lo : b_hi;
        uint32_t sa = sb + S_BUF0 + buf * BUFSZ;
        uint32_t sB = sa + ASZ;
        // A: 66 rows x 64B = 264 cp16 ops
        for (int idx = tid; idx < 264; idx += 256) {
            int r = idx >> 2, c = idx & 3;
            int l = l0 - 1 + r;
            int v = ((unsigned)l < 512u) ? 1 : 0;
            long grow = (long)row0 - 1 + r;
            const __nv_bfloat16* src = ap + (v ? (grow * 256 + kc * 32 + c * 8) : 0);
            cp16(sa + (uint32_t)(r * 80 + c * 16), src, v);
        }
        // B: contiguous 48KB block = 3072 cp16 ops (12/thread, coalesced)
        const __nv_bfloat16* bbase = bp + (size_t)kc * 24576;
#pragma unroll
        for (int i = 0; i < 12; i++) {
            int u = i * 256 + tid;
            int f = u / 12, rem = u % 12;
            int tap = rem >> 2, c = rem & 3;
            cp16(sB + (uint32_t)(f * 208 + tap * 64 + c * 16), bbase + u * 8, 1);
        }
        cp_commit();
    };

    stage(0);

    for (int it = 0; it < 24; it++) {
        if (it + 1 < 24) stage(it + 1);
        if (it + 1 < 24) cp_wait1(); else cp_wait0();
        __syncthreads();

        const uint32_t Ab = sb + S_BUF0 + (uint32_t)(it & 1) * BUFSZ;
        const uint32_t Bb = Ab + ASZ;
#pragma unroll
        for (int tap = 0; tap < 3; tap++) {
#pragma unroll
            for (int ko = 0; ko < 2; ko++) {
                uint32_t a[2][4];
#pragma unroll
                for (int tm = 0; tm < 2; tm++)
                    ldsm4(a[tm], Ab + aL + (uint32_t)(tm * 1280 + tap * 80 + ko * 32));
                uint32_t b[8][2];
#pragma unroll
                for (int g = 0; g < 4; g++) {
                    uint32_t r[4];
                    ldsm4(r, Bb + bL + (uint32_t)(g * 3328 + tap * 64 + ko * 32));
                    b[2 * g][0] = r[0];
                    b[2 * g][1] = r[1];
                    b[2 * g + 1][0] = r[2];
                    b[2 * g + 1][1] = r[3];
                }
#pragma unroll
                for (int tm = 0; tm < 2; tm++)
#pragma unroll
                    for (int tn = 0; tn < 8; tn++)
                        mma16816(d[tm][tn], a[tm], b[tn]);
            }
        }
        __syncthreads();
    }

    // -------- epilogue: accums -> smem stats, LN per row --------
    float* stats = (float*)(sm + S_BUF0);       // 64 x 264 fp32 (reuses buffers)
#pragma unroll
    for (int tm = 0; tm < 2; tm++) {
#pragma unroll
        for (int tn = 0; tn < 8; tn++) {
            int m = wm * 32 + tm * 16 + (lane >> 2);
            int n = wn * 64 + tn * 8 + (lane & 3) * 2;
            stats[m * 264 + n] = d[tm][tn][0] + s_bias[n];
            stats[m * 264 + n + 1] = d[tm][tn][1] + s_bias[n + 1];
            stats[(m + 8) * 264 + n] = d[tm][tn][2] + s_bias[n];
            stats[(m + 8) * 264 + n + 1] = d[tm][tn][3] + s_bias[n + 1];
        }
    }
    __syncthreads();

    const int row = tid >> 2, q = tid & 3;
    const float* rp = stats + row * 264 + q * 64;
    float sum = 0.f, ssq = 0.f;
#pragma unroll 8
    for (int i = 0; i < 64; i++) {
        float v = rp[i];
        sum += v;
        ssq = fmaf(v, v, ssq);
    }
    sum += __shfl_xor_sync(0xffffffffu, sum, 1);
    ssq += __shfl_xor_sync(0xffffffffu, ssq, 1);
    sum += __shfl_xor_sync(0xffffffffu, sum, 2);
    ssq += __shfl_xor_sync(0xffffffffu, ssq, 2);
    float mu = sum * (1.f / 256.f);
    float rs = rsqrtf(ssq * (1.f / 256.f) - mu * mu + EPSV);

    if (mode == 1) {
        float dot = 0.f;
#pragma unroll 8
        for (int i = 0; i < 64; i++) {
            int c = q * 64 + i;
            float y = fmaxf((rp[i] - mu) * rs * s_g[c] + s_be[c], 0.f);
            dot = fmaf(y, s_lw[c], dot);
        }
        dot += __shfl_xor_sync(0xffffffffu, dot, 1);
        dot += __shfl_xor_sync(0xffffffffu, dot, 2);
        if (q == 0) dup[row0 + row] = fmaxf(dot + lb[0], 0.f);
    } else {
        // 8 x (8 bf16) vector stores per thread for hi and lo
#pragma unroll
        for (int v8 = 0; v8 < 8; v8++) {
            __nv_bfloat16 h[8], l[8];
#pragma unroll
            for (int j = 0; j < 8; j++) {
                int c = q * 64 + v8 * 8 + j;
                float y = fmaxf((rp[v8 * 8 + j] - mu) * rs * s_g[c] + s_be[c], 0.f);
                h[j] = __float2bfloat16(y);
                l[j] = __float2bfloat16(y - __bfloat162float(h[j]));
            }
            size_t go = (size_t)(row0 + row) * 256 + q * 64 + v8 * 8;
            *(uint4*)(out_hi + go) = *(uint4*)h;
            *(uint4*)(out_lo + go) = *(uint4*)l;
        }
    }
}

// ---------------------------------------------------------------------------
extern "C" void kernel_launch(void* const* d_in, const int* in_sizes, int n_in,
                              void* d_out, int out_size) {
    const float* x      = (const float*)d_in[0];
    const int*   target = (const int*)d_in[1];
    const float* w1  = (const float*)d_in[3];
    const float* b1  = (const float*)d_in[4];
    const float* g1  = (const float*)d_in[5];
    const float* be1 = (const float*)d_in[6];
    const float* w2  = (const float*)d_in[7];
    const float* b2  = (const float*)d_in[8];
    const float* g2  = (const float*)d_in[9];
    const float* be2 = (const float*)d_in[10];
    const float* lw  = (const float*)d_in[11];
    const float* lb  = (const float*)d_in[12];

    float* out = (float*)d_out;
    float* dup = out + (size_t)BB * MM * DD;

    __nv_bfloat16 *xhi, *xlo, *h1hi, *h1lo, *B1h, *B1l, *B2h, *B2l;
    int* cs;
    cudaGetSymbolAddress((void**)&xhi, g_xhi);
    cudaGetSymbolAddress((void**)&xlo, g_xlo);
    cudaGetSymbolAddress((void**)&h1hi, g_h1hi);
    cudaGetSymbolAddress((void**)&h1lo, g_h1lo);
    cudaGetSymbolAddress((void**)&B1h, g_B1h);
    cudaGetSymbolAddress((void**)&B1l, g_B1l);
    cudaGetSymbolAddress((void**)&B2h, g_B2h);
    cudaGetSymbolAddress((void**)&B2l, g_B2l);
    cudaGetSymbolAddress((void**)&cs, g_cs);

    cudaFuncSetAttribute((const void*)conv_mma,
                         cudaFuncAttributeMaxDynamicSharedMemorySize, S_TOTAL);

    prep_convert<<<(BB * LL * DD + 255) / 256, 256>>>(x, w1, w2);
    cumsum_k<<<BB, LL>>>(target, cs);
    regulate<<<BB * MM / 8, 256>>>(x, cs, out);

    conv_mma<<<BB * LL / 64, 256, S_TOTAL>>>(xhi, xlo, B1h, B1l, b1, g1, be1, 0,
                                             h1hi, h1lo, lw, lb, dup);
    conv_mma<<<BB * LL / 64, 256, S_TOTAL>>>(h1hi, h1lo, B2h, B2l, b2, g2, be2, 1,
                                             h1hi, h1lo, lw, lb, dup);
}